// round 14
// baseline (speedup 1.0000x reference)
#include <cuda_runtime.h>
#include <cuda_bf16.h>
#include <cuda_fp16.h>
#include <cstdint>

// ---------------- problem constants ----------------
#define NODE_DIM 128
#define CTX_DIM  256
#define OUT_DIM  256
#define IN_DIM   384
#define N_COEF   7
#define K_TOTAL  3072        // plane-major: plane j at j*384 + i (j=0 silu, j=1..7 coefs)
#define MAX_EDGES 100000

// ---------------- device scratch (static) ----------------
__device__ half  g_act_h[(size_t)MAX_EDGES * K_TOTAL];    // 614 MB
__device__ half  g_w_h[(size_t)OUT_DIM * K_TOTAL];
__device__ half  g_cemb_h[(size_t)MAX_EDGES * CTX_DIM];   // 51 MB
__device__ half  g_cw_h[(size_t)NODE_DIM * CTX_DIM];
__device__ half  g_cw_l[(size_t)NODE_DIM * CTX_DIM];
__device__ unsigned int g_tile_ctr;

// ---------------- helpers ----------------
__device__ __forceinline__ uint32_t smem_u32(const void* p) {
    uint32_t a;
    asm("{ .reg .u64 t; cvta.to.shared.u64 t, %1; cvt.u32.u64 %0, t; }" : "=r"(a) : "l"(p));
    return a;
}
#define SWZ(x) ((x) ^ (((x) >> 3) & 0x70))

__device__ __forceinline__ void cp16(uint32_t saddr, const void* g, uint32_t sz) {
    asm volatile("cp.async.cg.shared.global [%0], [%1], 16, %2;\n"
                 :: "r"(saddr), "l"(g), "r"(sz));
}
template <int N>
__device__ __forceinline__ void cp_wait() {
    asm volatile("cp.async.wait_group %0;\n" :: "n"(N) : "memory");
}
__device__ __forceinline__ void cp_commit() {
    asm volatile("cp.async.commit_group;\n" ::: "memory");
}

__device__ __forceinline__ void ldm4(uint32_t* r, uint32_t addr) {
    asm volatile("ldmatrix.sync.aligned.m8n8.x4.shared.b16 {%0,%1,%2,%3}, [%4];"
                 : "=r"(r[0]), "=r"(r[1]), "=r"(r[2]), "=r"(r[3]) : "r"(addr));
}

__device__ __forceinline__ void mma_f16(float* d, const uint32_t* a, const uint32_t* b) {
    asm volatile(
        "mma.sync.aligned.m16n8k16.row.col.f32.f16.f16.f32 "
        "{%0,%1,%2,%3}, {%4,%5,%6,%7}, {%8,%9}, {%0,%1,%2,%3};"
        : "+f"(d[0]), "+f"(d[1]), "+f"(d[2]), "+f"(d[3])
        : "r"(a[0]), "r"(a[1]), "r"(a[2]), "r"(a[3]), "r"(b[0]), "r"(b[1]));
}

__device__ __forceinline__ uint32_t pack_half2(float lo, float hi) {
    __half2 h;
    h.x = __float2half_rn(lo);
    h.y = __float2half_rn(hi);
    return *reinterpret_cast<uint32_t*>(&h);
}

// silu + cardinal cubic B-spline weights for one x (verified path)
__device__ __forceinline__ void silu_spline(float x, float g0, float rh, float* v8)
{
    v8[0] = x / (1.f + __expf(-x));
    float d = (x - g0) * rh;
    float fj = floorf(d);
    int js = (int)fj;
    float u = d - fj;
    bool inr = (d >= 0.f) && (js <= 9);
    float u2 = u * u, u3 = u2 * u;
    float om = 1.f - u;
    float c0 = om * om * om * (1.f / 6.f);
    float c1 = (3.f * u3 - 6.f * u2 + 4.f) * (1.f / 6.f);
    float c2 = (-3.f * u3 + 3.f * u2 + 3.f * u + 1.f) * (1.f / 6.f);
    float c3 = u3 * (1.f / 6.f);
#pragma unroll
    for (int j = 0; j < N_COEF; ++j) {
        int r = j - js + 3;
        float w = 0.f;
        w = (r == 0) ? c0 : w;
        w = (r == 1) ? c1 : w;
        w = (r == 2) ? c2 : w;
        w = (r == 3) ? c3 : w;
        v8[1 + j] = inr ? w : 0.f;
    }
}

// ---------------- fused prep: weff fp16 + ctxw fp16 hi/lo + cemb fp16 -------
__global__ void prep_all(const float* __restrict__ bw, const float* __restrict__ sw,
                         const float* __restrict__ ss, half* __restrict__ Wh,
                         const float* __restrict__ ctxw, half* __restrict__ cwh,
                         half* __restrict__ cwl,
                         const float* __restrict__ cemb, half* __restrict__ ceh,
                         int nCemb8)
{
    int t = blockIdx.x * blockDim.x + threadIdx.x;
    const int T1 = OUT_DIM * K_TOTAL;
    const int T2 = (NODE_DIM * CTX_DIM) / 4;

    if (t < T1) {
        int o = t / K_TOTAL;
        int k = t - o * K_TOTAL;
        float v;
        if (k < IN_DIM) v = bw[o * IN_DIM + k];
        else {
            int r = k - IN_DIM;
            int c = r / IN_DIM;
            int i = r - c * IN_DIM;
            v = sw[((size_t)o * IN_DIM + i) * N_COEF + c] * ss[o * IN_DIM + i];
        }
        Wh[t] = __float2half_rn(v);
        return;
    }
    t -= T1;
    if (t < T2) {
        float4 v = *reinterpret_cast<const float4*>(ctxw + t * 4);
        float f[4] = {v.x, v.y, v.z, v.w};
        float h[4], l[4];
#pragma unroll
        for (int q = 0; q < 4; ++q) {
            half b = __float2half_rn(f[q]);
            h[q] = __half2float(b);
            l[q] = f[q] - h[q];
        }
        *reinterpret_cast<uint2*>(cwh + t * 4) =
            make_uint2(pack_half2(h[0], h[1]), pack_half2(h[2], h[3]));
        *reinterpret_cast<uint2*>(cwl + t * 4) =
            make_uint2(pack_half2(l[0], l[1]), pack_half2(l[2], l[3]));
        return;
    }
    t -= T2;
    if (t < nCemb8) {
        const float4* p = reinterpret_cast<const float4*>(cemb) + (size_t)t * 2;
        float4 a = p[0], b = p[1];
        uint4 o;
        o.x = pack_half2(a.x, a.y);
        o.y = pack_half2(a.z, a.w);
        o.z = pack_half2(b.x, b.y);
        o.w = pack_half2(b.z, b.w);
        *reinterpret_cast<uint4*>(ceh + (size_t)t * 8) = o;
    }
}

// ---------------- build_act for node-sourced dims (i < 256) -----------------
__global__ void build_act_node(const float* __restrict__ node,
                               const int* __restrict__ pairs,
                               const float* __restrict__ gridp,
                               half* __restrict__ acth, int nEdges)
{
    int t = blockIdx.x * blockDim.x + threadIdx.x;
    if (t >= nEdges * 32) return;
    int n = t / 32;
    int sub = t - n * 32;
    int i0 = sub * 8;                    // 0..248

    const float g0 = gridp[0];
    const float rh = 1.f / (gridp[1] - g0);

    const float* src;
    if (i0 < NODE_DIM)
        src = node + (size_t)pairs[2 * n] * NODE_DIM + i0;
    else
        src = node + (size_t)pairs[2 * n + 1] * NODE_DIM + (i0 - NODE_DIM);

    float4 xa = *reinterpret_cast<const float4*>(src);
    float4 xb = *reinterpret_cast<const float4*>(src + 4);
    float xs[8] = {xa.x, xa.y, xa.z, xa.w, xb.x, xb.y, xb.z, xb.w};

    uint32_t pl[8][4];
#pragma unroll
    for (int q = 0; q < 4; ++q) {
        float v0[8], v1[8];
        silu_spline(xs[2 * q], g0, rh, v0);
        silu_spline(xs[2 * q + 1], g0, rh, v1);
#pragma unroll
        for (int j = 0; j < 8; ++j)
            pl[j][q] = pack_half2(v0[j], v1[j]);
    }

    size_t base = (size_t)n * K_TOTAL;
#pragma unroll
    for (int j = 0; j < 8; ++j)
        *reinterpret_cast<uint4*>(acth + base + (size_t)j * IN_DIM + i0) =
            make_uint4(pl[j][0], pl[j][1], pl[j][2], pl[j][3]);
}

// ============ ctx GEMM fused: fp16 2-pass + spline epilogue -> act planes ===
// xc tile computed in accumulators, staged to smem (f32), then silu+spline
// written directly into act planes for i in [256, 384).
#define COFF_A  0
#define COFF_BH 16384
#define COFF_BL 32768
#define CSTAGE  49152
#define SMEM_CTX (3 * 49152)      // 144 KB (epilogue reuses 67.6 KB of it)

__global__ void __launch_bounds__(256, 1)
ctx_gemm_fused(const half* __restrict__ A, const half* __restrict__ Bh,
               const half* __restrict__ Bl, const float* __restrict__ bias,
               const float* __restrict__ gridp, half* __restrict__ acth,
               int M, int K)
{
    extern __shared__ char smem[];
    const uint32_t sbase = smem_u32(smem);
    float* smf = reinterpret_cast<float*>(smem);   // 128 x 132 floats
    const int tid = threadIdx.x;
    const int wid = tid >> 5;
    const int lid = tid & 31;
    const int m0 = blockIdx.x * 128;
    const int warp_m = (wid >> 2) * 64;
    const int warp_n = (wid & 3) * 32;

    float acc[4][4][4];
#pragma unroll
    for (int i = 0; i < 4; ++i)
#pragma unroll
        for (int j = 0; j < 4; ++j)
#pragma unroll
            for (int q = 0; q < 4; ++q) acc[i][j][q] = 0.f;

    auto load_stage = [&](int t, int buf) {
        const uint32_t bb = sbase + buf * CSTAGE;
        const int k0 = t * 64;
        for (int i = tid; i < 1024; i += 256) {
            int row = i >> 3, c = i & 7;
            int m = m0 + row;
            uint32_t v = (m < M) ? 16u : 0u;
            size_t go = (size_t)(m < M ? m : 0) * K + k0 + c * 8;
            uint32_t so = SWZ(row * 128 + c * 16);
            cp16(bb + COFF_A + so, A + go, v);
        }
        for (int i = tid; i < 1024; i += 256) {
            int row = i >> 3, c = i & 7;
            size_t go = (size_t)row * K + k0 + c * 8;   // N=128 rows, all valid
            uint32_t so = SWZ(row * 128 + c * 16);
            cp16(bb + COFF_BH + so, Bh + go, 16u);
            cp16(bb + COFF_BL + so, Bl + go, 16u);
        }
        cp_commit();
    };

    const int nk = K / 64;   // 4
    load_stage(0, 0);
    load_stage(1, 1);

    for (int t = 0; t < nk; ++t) {
        if (t < nk - 1) cp_wait<1>(); else cp_wait<0>();
        __syncthreads();
        if (t + 2 < nk) load_stage(t + 2, (t + 2) % 3);

        const uint32_t bb = sbase + (t % 3) * CSTAGE;
#pragma unroll
        for (int ks = 0; ks < 4; ++ks) {
            uint32_t ah[4][4], bh[4][2], bl[4][2];
            {
                uint32_t row_in = ((lid >> 3) & 1) * 8 + (lid & 7);
                uint32_t kb = ks * 32 + (lid >> 4) * 16;
#pragma unroll
                for (int mf = 0; mf < 4; ++mf) {
                    uint32_t off = SWZ((warp_m + mf * 16 + row_in) * 128 + kb);
                    ldm4(ah[mf], bb + COFF_A + off);
                }
            }
            {
                uint32_t row_in = ((lid >> 4) & 1) * 8 + (lid & 7);
                uint32_t kb = ks * 32 + ((lid >> 3) & 1) * 16;
#pragma unroll
                for (int p = 0; p < 2; ++p) {
                    uint32_t off = SWZ((warp_n + p * 16 + row_in) * 128 + kb);
                    uint32_t r[4];
                    ldm4(r, bb + COFF_BH + off);
                    bh[2 * p][0] = r[0]; bh[2 * p][1] = r[1];
                    bh[2 * p + 1][0] = r[2]; bh[2 * p + 1][1] = r[3];
                    ldm4(r, bb + COFF_BL + off);
                    bl[2 * p][0] = r[0]; bl[2 * p][1] = r[1];
                    bl[2 * p + 1][0] = r[2]; bl[2 * p + 1][1] = r[3];
                }
            }
#pragma unroll
            for (int mf = 0; mf < 4; ++mf)
#pragma unroll
                for (int nf = 0; nf < 4; ++nf)
                    mma_f16(acc[mf][nf], ah[mf], bh[nf]);
#pragma unroll
            for (int mf = 0; mf < 4; ++mf)
#pragma unroll
                for (int nf = 0; nf < 4; ++nf)
                    mma_f16(acc[mf][nf], ah[mf], bl[nf]);
        }
        __syncthreads();
    }

    // ---- stage xc tile (f32, +bias applied later) into smem, stride 132 ----
#pragma unroll
    for (int mf = 0; mf < 4; ++mf) {
        int r0 = warp_m + mf * 16 + (lid >> 2);
        int col = warp_n + ((lid & 3) << 1);
#pragma unroll
        for (int nf = 0; nf < 4; ++nf) {
            int c = col + nf * 8;
            *reinterpret_cast<float2*>(&smf[r0 * 132 + c]) =
                make_float2(acc[mf][nf][0], acc[mf][nf][1]);
            *reinterpret_cast<float2*>(&smf[(r0 + 8) * 132 + c]) =
                make_float2(acc[mf][nf][2], acc[mf][nf][3]);
        }
    }
    __syncthreads();

    // ---- vectorized spline epilogue: 2048 (row, i-group) tasks ----
    const float g0 = gridp[0];
    const float rh = 1.f / (gridp[1] - g0);
#pragma unroll
    for (int it = 0; it < 8; ++it) {
        int tt = tid + it * 256;
        int row = tt >> 4;
        int i0 = (tt & 15) * 8;          // local i in [0,128)
        int edge = m0 + row;
        if (edge >= M) continue;

        float xs[8];
#pragma unroll
        for (int e = 0; e < 8; ++e)
            xs[e] = smf[row * 132 + i0 + e] + bias[i0 + e];

        uint32_t pl[8][4];
#pragma unroll
        for (int q = 0; q < 4; ++q) {
            float v0[8], v1[8];
            silu_spline(xs[2 * q], g0, rh, v0);
            silu_spline(xs[2 * q + 1], g0, rh, v1);
#pragma unroll
            for (int j = 0; j < 8; ++j)
                pl[j][q] = pack_half2(v0[j], v1[j]);
        }

        size_t base = (size_t)edge * K_TOTAL + 256 + i0;   // i_global = 256+i0
#pragma unroll
        for (int j = 0; j < 8; ++j)
            *reinterpret_cast<uint4*>(acth + base + (size_t)j * IN_DIM) =
                make_uint4(pl[j][0], pl[j][1], pl[j][2], pl[j][3]);
    }
}

// ============ main GEMM: plain fp16 single pass, persistent + dynamic =======
#define MOFF_AH 0
#define MOFF_BH 16384
#define MSTAGE  32768
#define SMEM_MAIN (3 * 32768)     // 96 KB -> 2 CTAs/SM

__global__ void __launch_bounds__(256, 2)
main_gemm(const half* __restrict__ Ah, const half* __restrict__ Bh,
          float* __restrict__ C, int M, int ntiles)
{
    extern __shared__ char smem[];
    __shared__ unsigned int s_tile;
    const uint32_t sbase = smem_u32(smem);
    const int tid = threadIdx.x;
    const int wid = tid >> 5;
    const int lid = tid & 31;
    const int warp_m = (wid >> 2) * 64;
    const int warp_n = (wid & 3) * 32;
    const int nk = K_TOTAL / 64;   // 48

    auto load_stage = [&](int m0, int n0, int t, int buf) {
        const uint32_t bb = sbase + buf * MSTAGE;
        const int k0 = t * 64;
        for (int i = tid; i < 1024; i += 256) {
            int row = i >> 3, c = i & 7;
            int m = m0 + row;
            uint32_t v = (m < M) ? 16u : 0u;
            uint32_t so = SWZ(row * 128 + c * 16);
            cp16(bb + MOFF_AH + so,
                 Ah + (size_t)(m < M ? m : 0) * K_TOTAL + k0 + c * 8, v);
        }
        for (int i = tid; i < 1024; i += 256) {
            int row = i >> 3, c = i & 7;
            size_t go = (size_t)(n0 + row) * K_TOTAL + k0 + c * 8;
            uint32_t so = SWZ(row * 128 + c * 16);
            cp16(bb + MOFF_BH + so, Bh + go, 16u);
        }
        cp_commit();
    };

    while (true) {
        if (tid == 0) s_tile = atomicAdd(&g_tile_ctr, 1u);
        __syncthreads();
        unsigned int tile = s_tile;
        if (tile >= (unsigned)ntiles) break;

        const int m0 = (int)(tile >> 1) * 128;
        const int n0 = (int)(tile & 1) * 128;

        float acc[4][4][4];
#pragma unroll
        for (int i = 0; i < 4; ++i)
#pragma unroll
            for (int j = 0; j < 4; ++j)
#pragma unroll
                for (int q = 0; q < 4; ++q) acc[i][j][q] = 0.f;

        load_stage(m0, n0, 0, 0);
        load_stage(m0, n0, 1, 1);

        for (int t = 0; t < nk; ++t) {
            if (t < nk - 1) cp_wait<1>(); else cp_wait<0>();
            __syncthreads();
            if (t + 2 < nk) load_stage(m0, n0, t + 2, (t + 2) % 3);

            const uint32_t bb = sbase + (t % 3) * MSTAGE;
#pragma unroll
            for (int ks = 0; ks < 4; ++ks) {
                uint32_t ah[4][4], bh[4][2];
                {
                    uint32_t row_in = ((lid >> 3) & 1) * 8 + (lid & 7);
                    uint32_t kb = ks * 32 + (lid >> 4) * 16;
#pragma unroll
                    for (int mf = 0; mf < 4; ++mf) {
                        uint32_t off = SWZ((warp_m + mf * 16 + row_in) * 128 + kb);
                        ldm4(ah[mf], bb + MOFF_AH + off);
                    }
                }
                {
                    uint32_t row_in = ((lid >> 4) & 1) * 8 + (lid & 7);
                    uint32_t kb = ks * 32 + ((lid >> 3) & 1) * 16;
#pragma unroll
                    for (int p = 0; p < 2; ++p) {
                        uint32_t off = SWZ((warp_n + p * 16 + row_in) * 128 + kb);
                        uint32_t r[4];
                        ldm4(r, bb + MOFF_BH + off);
                        bh[2 * p][0] = r[0]; bh[2 * p][1] = r[1];
                        bh[2 * p + 1][0] = r[2]; bh[2 * p + 1][1] = r[3];
                    }
                }
#pragma unroll
                for (int mf = 0; mf < 4; ++mf)
#pragma unroll
                    for (int nf = 0; nf < 4; ++nf)
                        mma_f16(acc[mf][nf], ah[mf], bh[nf]);
            }
        }

#pragma unroll
        for (int mf = 0; mf < 4; ++mf) {
            int r0 = m0 + warp_m + mf * 16 + (lid >> 2);
#pragma unroll
            for (int nf = 0; nf < 4; ++nf) {
                int col = n0 + warp_n + nf * 8 + (lid & 3) * 2;
                if (r0 < M) {
                    float2 v = make_float2(acc[mf][nf][0], acc[mf][nf][1]);
                    *reinterpret_cast<float2*>(&C[(size_t)r0 * OUT_DIM + col]) = v;
                }
                if (r0 + 8 < M) {
                    float2 v = make_float2(acc[mf][nf][2], acc[mf][nf][3]);
                    *reinterpret_cast<float2*>(&C[(size_t)(r0 + 8) * OUT_DIM + col]) = v;
                }
            }
        }
    }
}

// ---------------------------------------------------------------------------
extern "C" void kernel_launch(void* const* d_in, const int* in_sizes, int n_in,
                              void* d_out, int out_size)
{
    const float* node  = (const float*)d_in[0];
    const float* cemb  = (const float*)d_in[1];
    const int*   pairs = (const int*)  d_in[2];
    const float* ctxw  = (const float*)d_in[3];
    const float* ctxb  = (const float*)d_in[4];
    const float* bw    = (const float*)d_in[5];
    const float* sw    = (const float*)d_in[6];
    const float* ss    = (const float*)d_in[7];
    const float* grid  = (const float*)d_in[8];
    float* out = (float*)d_out;

    int nEdges = in_sizes[2] / 2;

    half *acth, *wh, *ceh, *cwh, *cwl;
    void* ctrp;
    cudaGetSymbolAddress((void**)&acth, g_act_h);
    cudaGetSymbolAddress((void**)&wh, g_w_h);
    cudaGetSymbolAddress((void**)&ceh, g_cemb_h);
    cudaGetSymbolAddress((void**)&cwh, g_cw_h);
    cudaGetSymbolAddress((void**)&cwl, g_cw_l);
    cudaGetSymbolAddress(&ctrp, g_tile_ctr);

    cudaFuncSetAttribute(ctx_gemm_fused, cudaFuncAttributeMaxDynamicSharedMemorySize, SMEM_CTX);
    cudaFuncSetAttribute(main_gemm, cudaFuncAttributeMaxDynamicSharedMemorySize, SMEM_MAIN);

    // reset dynamic-tile counter (async memset: graph-capturable, no alloc)
    cudaMemsetAsync(ctrp, 0, sizeof(unsigned int));

    // fused prep: weights + ctxw split + cemb convert
    {
        int nCemb8 = nEdges * CTX_DIM / 8;
        int total = OUT_DIM * K_TOTAL + (NODE_DIM * CTX_DIM) / 4 + nCemb8;
        prep_all<<<(total + 255) / 256, 256>>>(bw, sw, ss, wh, ctxw, cwh, cwl,
                                               cemb, ceh, nCemb8);
    }

    // node-sourced act planes (i < 256) — independent of ctx
    {
        int total = nEdges * 32;
        build_act_node<<<(total + 255) / 256, 256>>>(node, pairs, grid, acth, nEdges);
    }

    // ctx projection + fused silu/spline epilogue -> act planes i in [256,384)
    {
        int blocks = (nEdges + 127) / 128;
        ctx_gemm_fused<<<blocks, 256, SMEM_CTX>>>(ceh, cwh, cwl, ctxb, grid,
                                                  acth, nEdges, CTX_DIM);
    }

    // main GEMM  out = act @ weff^T  (M=nEdges, N=256, K=3072), dynamic tiles
    {
        int ntiles = ((nEdges + 127) / 128) * 2;
        int blocks = ntiles < 296 ? ntiles : 296;
        main_gemm<<<blocks, 256, SMEM_MAIN>>>(acth, wh, out, nEdges, ntiles);
    }
}

// round 15
// speedup vs baseline: 1.0973x; 1.0973x over previous
#include <cuda_runtime.h>
#include <cuda_bf16.h>
#include <cuda_fp16.h>
#include <cstdint>

// ---------------- problem constants ----------------
#define NODE_DIM 128
#define CTX_DIM  256
#define OUT_DIM  256
#define IN_DIM   384
#define N_COEF   7
#define K_TOTAL  3072        // plane-major: plane j at j*384 + i (j=0 silu, j=1..7 coefs)
#define MAX_EDGES 100000

// ---------------- device scratch (static) ----------------
__device__ float g_xc[(size_t)MAX_EDGES * NODE_DIM];
__device__ half  g_act_h[(size_t)MAX_EDGES * K_TOTAL];    // 614 MB
__device__ half  g_w_h[(size_t)OUT_DIM * K_TOTAL];
__device__ half  g_cemb_h[(size_t)MAX_EDGES * CTX_DIM];   // 51 MB
__device__ half  g_cw_h[(size_t)NODE_DIM * CTX_DIM];
__device__ half  g_cw_l[(size_t)NODE_DIM * CTX_DIM];

// ---------------- helpers ----------------
__device__ __forceinline__ uint32_t smem_u32(const void* p) {
    uint32_t a;
    asm("{ .reg .u64 t; cvta.to.shared.u64 t, %1; cvt.u32.u64 %0, t; }" : "=r"(a) : "l"(p));
    return a;
}
#define SWZ(x) ((x) ^ (((x) >> 3) & 0x70))

__device__ __forceinline__ void cp16(uint32_t saddr, const void* g, uint32_t sz) {
    asm volatile("cp.async.cg.shared.global [%0], [%1], 16, %2;\n"
                 :: "r"(saddr), "l"(g), "r"(sz));
}
template <int N>
__device__ __forceinline__ void cp_wait() {
    asm volatile("cp.async.wait_group %0;\n" :: "n"(N) : "memory");
}
__device__ __forceinline__ void cp_commit() {
    asm volatile("cp.async.commit_group;\n" ::: "memory");
}

__device__ __forceinline__ void ldm4(uint32_t* r, uint32_t addr) {
    asm volatile("ldmatrix.sync.aligned.m8n8.x4.shared.b16 {%0,%1,%2,%3}, [%4];"
                 : "=r"(r[0]), "=r"(r[1]), "=r"(r[2]), "=r"(r[3]) : "r"(addr));
}

__device__ __forceinline__ void mma_f16(float* d, const uint32_t* a, const uint32_t* b) {
    asm volatile(
        "mma.sync.aligned.m16n8k16.row.col.f32.f16.f16.f32 "
        "{%0,%1,%2,%3}, {%4,%5,%6,%7}, {%8,%9}, {%0,%1,%2,%3};"
        : "+f"(d[0]), "+f"(d[1]), "+f"(d[2]), "+f"(d[3])
        : "r"(a[0]), "r"(a[1]), "r"(a[2]), "r"(a[3]), "r"(b[0]), "r"(b[1]));
}

__device__ __forceinline__ uint32_t pack_half2(float lo, float hi) {
    __half2 h;
    h.x = __float2half_rn(lo);
    h.y = __float2half_rn(hi);
    return *reinterpret_cast<uint32_t*>(&h);
}

// silu + cardinal cubic B-spline weights for one x (verified path)
__device__ __forceinline__ void silu_spline(float x, float g0, float rh, float* v8)
{
    v8[0] = x / (1.f + __expf(-x));
    float d = (x - g0) * rh;
    float fj = floorf(d);
    int js = (int)fj;
    float u = d - fj;
    bool inr = (d >= 0.f) && (js <= 9);
    float u2 = u * u, u3 = u2 * u;
    float om = 1.f - u;
    float c0 = om * om * om * (1.f / 6.f);
    float c1 = (3.f * u3 - 6.f * u2 + 4.f) * (1.f / 6.f);
    float c2 = (-3.f * u3 + 3.f * u2 + 3.f * u + 1.f) * (1.f / 6.f);
    float c3 = u3 * (1.f / 6.f);
#pragma unroll
    for (int j = 0; j < N_COEF; ++j) {
        int r = j - js + 3;
        float w = 0.f;
        w = (r == 0) ? c0 : w;
        w = (r == 1) ? c1 : w;
        w = (r == 2) ? c2 : w;
        w = (r == 3) ? c3 : w;
        v8[1 + j] = inr ? w : 0.f;
    }
}

// ---------------- fused prep: weff fp16 + ctxw fp16 hi/lo + cemb fp16 -------
__global__ void prep_all(const float* __restrict__ bw, const float* __restrict__ sw,
                         const float* __restrict__ ss, half* __restrict__ Wh,
                         const float* __restrict__ ctxw, half* __restrict__ cwh,
                         half* __restrict__ cwl,
                         const float* __restrict__ cemb, half* __restrict__ ceh,
                         int nCemb8)
{
    int t = blockIdx.x * blockDim.x + threadIdx.x;
    const int T1 = OUT_DIM * K_TOTAL;
    const int T2 = (NODE_DIM * CTX_DIM) / 4;

    if (t < T1) {
        int o = t / K_TOTAL;
        int k = t - o * K_TOTAL;
        float v;
        if (k < IN_DIM) v = bw[o * IN_DIM + k];
        else {
            int r = k - IN_DIM;
            int c = r / IN_DIM;
            int i = r - c * IN_DIM;
            v = sw[((size_t)o * IN_DIM + i) * N_COEF + c] * ss[o * IN_DIM + i];
        }
        Wh[t] = __float2half_rn(v);
        return;
    }
    t -= T1;
    if (t < T2) {
        float4 v = *reinterpret_cast<const float4*>(ctxw + t * 4);
        float f[4] = {v.x, v.y, v.z, v.w};
        float h[4], l[4];
#pragma unroll
        for (int q = 0; q < 4; ++q) {
            half b = __float2half_rn(f[q]);
            h[q] = __half2float(b);
            l[q] = f[q] - h[q];
        }
        *reinterpret_cast<uint2*>(cwh + t * 4) =
            make_uint2(pack_half2(h[0], h[1]), pack_half2(h[2], h[3]));
        *reinterpret_cast<uint2*>(cwl + t * 4) =
            make_uint2(pack_half2(l[0], l[1]), pack_half2(l[2], l[3]));
        return;
    }
    t -= T2;
    if (t < nCemb8) {
        const float4* p = reinterpret_cast<const float4*>(cemb) + (size_t)t * 2;
        float4 a = p[0], b = p[1];
        uint4 o;
        o.x = pack_half2(a.x, a.y);
        o.y = pack_half2(a.z, a.w);
        o.z = pack_half2(b.x, b.y);
        o.w = pack_half2(b.z, b.w);
        *reinterpret_cast<uint4*>(ceh + (size_t)t * 8) = o;
    }
}

// ============ ctx GEMM: fp16 2-pass (A plain, B hi/lo corrected) ============
#define COFF_A  0
#define COFF_BH 16384
#define COFF_BL 32768
#define CSTAGE  49152
#define SMEM_CTX (3 * 49152)      // 144 KB

__global__ void __launch_bounds__(256, 1)
ctx_gemm(const half* __restrict__ A, const half* __restrict__ Bh,
         const half* __restrict__ Bl, const float* __restrict__ bias,
         float* __restrict__ C, int M, int N, int K)
{
    extern __shared__ char smem[];
    const uint32_t sbase = smem_u32(smem);
    const int tid = threadIdx.x;
    const int wid = tid >> 5;
    const int lid = tid & 31;
    const int m0 = blockIdx.y * 128;
    const int n0 = blockIdx.x * 128;
    const int warp_m = (wid >> 2) * 64;
    const int warp_n = (wid & 3) * 32;

    float acc[4][4][4];
#pragma unroll
    for (int i = 0; i < 4; ++i)
#pragma unroll
        for (int j = 0; j < 4; ++j)
#pragma unroll
            for (int q = 0; q < 4; ++q) acc[i][j][q] = 0.f;

    auto load_stage = [&](int t, int buf) {
        const uint32_t bb = sbase + buf * CSTAGE;
        const int k0 = t * 64;
        for (int i = tid; i < 1024; i += 256) {
            int row = i >> 3, c = i & 7;
            int m = m0 + row;
            uint32_t v = (m < M) ? 16u : 0u;
            size_t go = (size_t)(m < M ? m : 0) * K + k0 + c * 8;
            uint32_t so = SWZ(row * 128 + c * 16);
            cp16(bb + COFF_A + so, A + go, v);
        }
        for (int i = tid; i < 1024; i += 256) {
            int row = i >> 3, c = i & 7;
            size_t go = (size_t)(n0 + row) * K + k0 + c * 8;
            uint32_t so = SWZ(row * 128 + c * 16);
            cp16(bb + COFF_BH + so, Bh + go, 16u);
            cp16(bb + COFF_BL + so, Bl + go, 16u);
        }
        cp_commit();
    };

    const int nk = K / 64;
    load_stage(0, 0);
    if (nk > 1) load_stage(1, 1);

    for (int t = 0; t < nk; ++t) {
        if (t < nk - 1) cp_wait<1>(); else cp_wait<0>();
        __syncthreads();
        if (t + 2 < nk) load_stage(t + 2, (t + 2) % 3);

        const uint32_t bb = sbase + (t % 3) * CSTAGE;
#pragma unroll
        for (int ks = 0; ks < 4; ++ks) {
            uint32_t ah[4][4], bh[4][2], bl[4][2];
            {
                uint32_t row_in = ((lid >> 3) & 1) * 8 + (lid & 7);
                uint32_t kb = ks * 32 + (lid >> 4) * 16;
#pragma unroll
                for (int mf = 0; mf < 4; ++mf) {
                    uint32_t off = SWZ((warp_m + mf * 16 + row_in) * 128 + kb);
                    ldm4(ah[mf], bb + COFF_A + off);
                }
            }
            {
                uint32_t row_in = ((lid >> 4) & 1) * 8 + (lid & 7);
                uint32_t kb = ks * 32 + ((lid >> 3) & 1) * 16;
#pragma unroll
                for (int p = 0; p < 2; ++p) {
                    uint32_t off = SWZ((warp_n + p * 16 + row_in) * 128 + kb);
                    uint32_t r[4];
                    ldm4(r, bb + COFF_BH + off);
                    bh[2 * p][0] = r[0]; bh[2 * p][1] = r[1];
                    bh[2 * p + 1][0] = r[2]; bh[2 * p + 1][1] = r[3];
                    ldm4(r, bb + COFF_BL + off);
                    bl[2 * p][0] = r[0]; bl[2 * p][1] = r[1];
                    bl[2 * p + 1][0] = r[2]; bl[2 * p + 1][1] = r[3];
                }
            }
#pragma unroll
            for (int mf = 0; mf < 4; ++mf)
#pragma unroll
                for (int nf = 0; nf < 4; ++nf)
                    mma_f16(acc[mf][nf], ah[mf], bh[nf]);
#pragma unroll
            for (int mf = 0; mf < 4; ++mf)
#pragma unroll
                for (int nf = 0; nf < 4; ++nf)
                    mma_f16(acc[mf][nf], ah[mf], bl[nf]);
        }
        __syncthreads();
    }

#pragma unroll
    for (int mf = 0; mf < 4; ++mf) {
        int r0 = m0 + warp_m + mf * 16 + (lid >> 2);
#pragma unroll
        for (int nf = 0; nf < 4; ++nf) {
            int col = n0 + warp_n + nf * 8 + (lid & 3) * 2;
            float b0 = bias ? bias[col] : 0.f;
            float b1 = bias ? bias[col + 1] : 0.f;
            if (r0 < M) {
                float2 v = make_float2(acc[mf][nf][0] + b0, acc[mf][nf][1] + b1);
                *reinterpret_cast<float2*>(&C[(size_t)r0 * N + col]) = v;
            }
            if (r0 + 8 < M) {
                float2 v = make_float2(acc[mf][nf][2] + b0, acc[mf][nf][3] + b1);
                *reinterpret_cast<float2*>(&C[(size_t)(r0 + 8) * N + col]) = v;
            }
        }
    }
}

// ============ main GEMM: fp16 single pass, 64x64 warp tiles ==================
// 128 threads = 4 warps in 2x2; each warp owns 64x64. Cuts ldmatrix traffic
// from 156 B/cyc/SM (over crossbar cap) to 94 B/cyc/SM.
// Stage = 32 KB; 3 stages = 96 KB -> 2 CTAs/SM (8 warps/SM).
#define MOFF_AH 0
#define MOFF_BH 16384
#define MSTAGE  32768
#define SMEM_MAIN (3 * 32768)

__global__ void __launch_bounds__(128, 2)
main_gemm(const half* __restrict__ Ah, const half* __restrict__ Bh,
          float* __restrict__ C, int M, int ntiles)
{
    extern __shared__ char smem[];
    const uint32_t sbase = smem_u32(smem);
    const int tid = threadIdx.x;
    const int wid = tid >> 5;
    const int lid = tid & 31;
    const int warp_m = (wid >> 1) * 64;   // 2 warp-rows of 64
    const int warp_n = (wid & 1) * 64;    // 2 warp-cols of 64
    const int nk = K_TOTAL / 64;          // 48

    auto load_stage = [&](int m0, int n0, int t, int buf) {
        const uint32_t bb = sbase + buf * MSTAGE;
        const int k0 = t * 64;
        for (int i = tid; i < 1024; i += 128) {
            int row = i >> 3, c = i & 7;
            int m = m0 + row;
            uint32_t v = (m < M) ? 16u : 0u;
            uint32_t so = SWZ(row * 128 + c * 16);
            cp16(bb + MOFF_AH + so,
                 Ah + (size_t)(m < M ? m : 0) * K_TOTAL + k0 + c * 8, v);
        }
        for (int i = tid; i < 1024; i += 128) {
            int row = i >> 3, c = i & 7;
            size_t go = (size_t)(n0 + row) * K_TOTAL + k0 + c * 8;
            uint32_t so = SWZ(row * 128 + c * 16);
            cp16(bb + MOFF_BH + so, Bh + go, 16u);
        }
        cp_commit();
    };

    for (int tile = blockIdx.x; tile < ntiles; tile += gridDim.x) {
        const int m0 = (tile >> 1) * 128;
        const int n0 = (tile & 1) * 128;

        float acc[4][8][4];
#pragma unroll
        for (int i = 0; i < 4; ++i)
#pragma unroll
            for (int j = 0; j < 8; ++j)
#pragma unroll
                for (int q = 0; q < 4; ++q) acc[i][j][q] = 0.f;

        load_stage(m0, n0, 0, 0);
        load_stage(m0, n0, 1, 1);

        for (int t = 0; t < nk; ++t) {
            if (t < nk - 1) cp_wait<1>(); else cp_wait<0>();
            __syncthreads();
            if (t + 2 < nk) load_stage(m0, n0, t + 2, (t + 2) % 3);

            const uint32_t bb = sbase + (t % 3) * MSTAGE;
#pragma unroll
            for (int ks = 0; ks < 4; ++ks) {
                uint32_t ah[4][4], bh[8][2];
                {
                    uint32_t row_in = ((lid >> 3) & 1) * 8 + (lid & 7);
                    uint32_t kb = ks * 32 + (lid >> 4) * 16;
#pragma unroll
                    for (int mf = 0; mf < 4; ++mf) {
                        uint32_t off = SWZ((warp_m + mf * 16 + row_in) * 128 + kb);
                        ldm4(ah[mf], bb + MOFF_AH + off);
                    }
                }
                {
                    uint32_t row_in = ((lid >> 4) & 1) * 8 + (lid & 7);
                    uint32_t kb = ks * 32 + ((lid >> 3) & 1) * 16;
#pragma unroll
                    for (int p = 0; p < 4; ++p) {
                        uint32_t off = SWZ((warp_n + p * 16 + row_in) * 128 + kb);
                        uint32_t r[4];
                        ldm4(r, bb + MOFF_BH + off);
                        bh[2 * p][0] = r[0]; bh[2 * p][1] = r[1];
                        bh[2 * p + 1][0] = r[2]; bh[2 * p + 1][1] = r[3];
                    }
                }
#pragma unroll
                for (int mf = 0; mf < 4; ++mf)
#pragma unroll
                    for (int nf = 0; nf < 8; ++nf)
                        mma_f16(acc[mf][nf], ah[mf], bh[nf]);
            }
        }

#pragma unroll
        for (int mf = 0; mf < 4; ++mf) {
            int r0 = m0 + warp_m + mf * 16 + (lid >> 2);
#pragma unroll
            for (int nf = 0; nf < 8; ++nf) {
                int col = n0 + warp_n + nf * 8 + (lid & 3) * 2;
                if (r0 < M) {
                    float2 v = make_float2(acc[mf][nf][0], acc[mf][nf][1]);
                    *reinterpret_cast<float2*>(&C[(size_t)r0 * OUT_DIM + col]) = v;
                }
                if (r0 + 8 < M) {
                    float2 v = make_float2(acc[mf][nf][2], acc[mf][nf][3]);
                    *reinterpret_cast<float2*>(&C[(size_t)(r0 + 8) * OUT_DIM + col]) = v;
                }
            }
        }
    }
}

// ---------------- activation builder: vectorized, cardinal spline -----------
__global__ void build_act(const float* __restrict__ node, const float* __restrict__ xc,
                          const int* __restrict__ pairs, const float* __restrict__ gridp,
                          half* __restrict__ acth, int nEdges)
{
    int t = blockIdx.x * blockDim.x + threadIdx.x;
    if (t >= nEdges * 48) return;
    int n = t / 48;
    int sub = t - n * 48;
    int i0 = sub * 8;

    const float g0 = gridp[0];
    const float rh = 1.f / (gridp[1] - g0);

    const float* src;
    if (i0 < NODE_DIM)
        src = node + (size_t)pairs[2 * n] * NODE_DIM + i0;
    else if (i0 < 2 * NODE_DIM)
        src = node + (size_t)pairs[2 * n + 1] * NODE_DIM + (i0 - NODE_DIM);
    else
        src = xc + (size_t)n * NODE_DIM + (i0 - 2 * NODE_DIM);

    float4 xa = *reinterpret_cast<const float4*>(src);
    float4 xb = *reinterpret_cast<const float4*>(src + 4);
    float xs[8] = {xa.x, xa.y, xa.z, xa.w, xb.x, xb.y, xb.z, xb.w};

    uint32_t pl[8][4];
#pragma unroll
    for (int q = 0; q < 4; ++q) {
        float v0[8], v1[8];
        silu_spline(xs[2 * q], g0, rh, v0);
        silu_spline(xs[2 * q + 1], g0, rh, v1);
#pragma unroll
        for (int j = 0; j < 8; ++j)
            pl[j][q] = pack_half2(v0[j], v1[j]);
    }

    size_t base = (size_t)n * K_TOTAL;
#pragma unroll
    for (int j = 0; j < 8; ++j)
        *reinterpret_cast<uint4*>(acth + base + (size_t)j * IN_DIM + i0) =
            make_uint4(pl[j][0], pl[j][1], pl[j][2], pl[j][3]);
}

// ---------------------------------------------------------------------------
extern "C" void kernel_launch(void* const* d_in, const int* in_sizes, int n_in,
                              void* d_out, int out_size)
{
    const float* node  = (const float*)d_in[0];
    const float* cemb  = (const float*)d_in[1];
    const int*   pairs = (const int*)  d_in[2];
    const float* ctxw  = (const float*)d_in[3];
    const float* ctxb  = (const float*)d_in[4];
    const float* bw    = (const float*)d_in[5];
    const float* sw    = (const float*)d_in[6];
    const float* ss    = (const float*)d_in[7];
    const float* grid  = (const float*)d_in[8];
    float* out = (float*)d_out;

    int nEdges = in_sizes[2] / 2;

    float *xc;
    half *acth, *wh, *ceh, *cwh, *cwl;
    cudaGetSymbolAddress((void**)&xc, g_xc);
    cudaGetSymbolAddress((void**)&acth, g_act_h);
    cudaGetSymbolAddress((void**)&wh, g_w_h);
    cudaGetSymbolAddress((void**)&ceh, g_cemb_h);
    cudaGetSymbolAddress((void**)&cwh, g_cw_h);
    cudaGetSymbolAddress((void**)&cwl, g_cw_l);

    cudaFuncSetAttribute(ctx_gemm, cudaFuncAttributeMaxDynamicSharedMemorySize, SMEM_CTX);
    cudaFuncSetAttribute(main_gemm, cudaFuncAttributeMaxDynamicSharedMemorySize, SMEM_MAIN);

    // fused prep: weights + ctxw split + cemb convert
    {
        int nCemb8 = nEdges * CTX_DIM / 8;
        int total = OUT_DIM * K_TOTAL + (NODE_DIM * CTX_DIM) / 4 + nCemb8;
        prep_all<<<(total + 255) / 256, 256>>>(bw, sw, ss, wh, ctxw, cwh, cwl,
                                               cemb, ceh, nCemb8);
    }

    // ctx projection  xc = cemb @ ctxw^T + b  (M=nEdges, N=128, K=256)
    {
        dim3 g(1, (nEdges + 127) / 128);
        ctx_gemm<<<g, 256, SMEM_CTX>>>(ceh, cwh, cwl, ctxb, xc,
                                       nEdges, NODE_DIM, CTX_DIM);
    }

    // activations (fp16, vectorized)
    {
        int total = nEdges * 48;
        build_act<<<(total + 255) / 256, 256>>>(node, xc, pairs, grid, acth, nEdges);
    }

    // main GEMM  out = act @ weff^T  (M=nEdges, N=256, K=3072), persistent
    {
        int ntiles = ((nEdges + 127) / 128) * 2;
        int blocks = ntiles < 296 ? ntiles : 296;
        main_gemm<<<blocks, 128, SMEM_MAIN>>>(acth, wh, out, nEdges, ntiles);
    }
}

// round 16
// speedup vs baseline: 1.1130x; 1.0143x over previous
#include <cuda_runtime.h>
#include <cuda_bf16.h>
#include <cuda_fp16.h>
#include <cstdint>

// ---------------- problem constants ----------------
#define NODE_DIM 128
#define CTX_DIM  256
#define OUT_DIM  256
#define IN_DIM   384
#define N_COEF   7
#define K_TOTAL  3072        // plane-major: plane j at j*384 + i (j=0 silu, j=1..7 coefs)
#define MAX_EDGES 100000

// ---------------- device scratch (static) ----------------
__device__ float g_xc[(size_t)MAX_EDGES * NODE_DIM];
__device__ half  g_act_h[(size_t)MAX_EDGES * K_TOTAL];    // 614 MB
__device__ half  g_w_h[(size_t)OUT_DIM * K_TOTAL];
__device__ half  g_cemb_h[(size_t)MAX_EDGES * CTX_DIM];   // 51 MB
__device__ half  g_cw_h[(size_t)NODE_DIM * CTX_DIM];

// ---------------- helpers ----------------
__device__ __forceinline__ uint32_t smem_u32(const void* p) {
    uint32_t a;
    asm("{ .reg .u64 t; cvta.to.shared.u64 t, %1; cvt.u32.u64 %0, t; }" : "=r"(a) : "l"(p));
    return a;
}
#define SWZ(x) ((x) ^ (((x) >> 3) & 0x70))

__device__ __forceinline__ void cp16(uint32_t saddr, const void* g, uint32_t sz) {
    asm volatile("cp.async.cg.shared.global [%0], [%1], 16, %2;\n"
                 :: "r"(saddr), "l"(g), "r"(sz));
}
template <int N>
__device__ __forceinline__ void cp_wait() {
    asm volatile("cp.async.wait_group %0;\n" :: "n"(N) : "memory");
}
__device__ __forceinline__ void cp_commit() {
    asm volatile("cp.async.commit_group;\n" ::: "memory");
}

__device__ __forceinline__ void ldm4(uint32_t* r, uint32_t addr) {
    asm volatile("ldmatrix.sync.aligned.m8n8.x4.shared.b16 {%0,%1,%2,%3}, [%4];"
                 : "=r"(r[0]), "=r"(r[1]), "=r"(r[2]), "=r"(r[3]) : "r"(addr));
}

__device__ __forceinline__ void mma_f16(float* d, const uint32_t* a, const uint32_t* b) {
    asm volatile(
        "mma.sync.aligned.m16n8k16.row.col.f32.f16.f16.f32 "
        "{%0,%1,%2,%3}, {%4,%5,%6,%7}, {%8,%9}, {%0,%1,%2,%3};"
        : "+f"(d[0]), "+f"(d[1]), "+f"(d[2]), "+f"(d[3])
        : "r"(a[0]), "r"(a[1]), "r"(a[2]), "r"(a[3]), "r"(b[0]), "r"(b[1]));
}

__device__ __forceinline__ uint32_t pack_half2(float lo, float hi) {
    __half2 h;
    h.x = __float2half_rn(lo);
    h.y = __float2half_rn(hi);
    return *reinterpret_cast<uint32_t*>(&h);
}

// silu + cardinal cubic B-spline weights for one x (verified path)
__device__ __forceinline__ void silu_spline(float x, float g0, float rh, float* v8)
{
    v8[0] = x / (1.f + __expf(-x));
    float d = (x - g0) * rh;
    float fj = floorf(d);
    int js = (int)fj;
    float u = d - fj;
    bool inr = (d >= 0.f) && (js <= 9);
    float u2 = u * u, u3 = u2 * u;
    float om = 1.f - u;
    float c0 = om * om * om * (1.f / 6.f);
    float c1 = (3.f * u3 - 6.f * u2 + 4.f) * (1.f / 6.f);
    float c2 = (-3.f * u3 + 3.f * u2 + 3.f * u + 1.f) * (1.f / 6.f);
    float c3 = u3 * (1.f / 6.f);
#pragma unroll
    for (int j = 0; j < N_COEF; ++j) {
        int r = j - js + 3;
        float w = 0.f;
        w = (r == 0) ? c0 : w;
        w = (r == 1) ? c1 : w;
        w = (r == 2) ? c2 : w;
        w = (r == 3) ? c3 : w;
        v8[1 + j] = inr ? w : 0.f;
    }
}

// ---------------- fused prep: weff fp16 + ctxw fp16 + cemb fp16 -------------
__global__ void prep_all(const float* __restrict__ bw, const float* __restrict__ sw,
                         const float* __restrict__ ss, half* __restrict__ Wh,
                         const float* __restrict__ ctxw, half* __restrict__ cwh,
                         const float* __restrict__ cemb, half* __restrict__ ceh,
                         int nCemb8)
{
    int t = blockIdx.x * blockDim.x + threadIdx.x;
    const int T1 = OUT_DIM * K_TOTAL;
    const int T2 = (NODE_DIM * CTX_DIM) / 4;

    if (t < T1) {
        int o = t / K_TOTAL;
        int k = t - o * K_TOTAL;
        float v;
        if (k < IN_DIM) v = bw[o * IN_DIM + k];
        else {
            int r = k - IN_DIM;
            int c = r / IN_DIM;
            int i = r - c * IN_DIM;
            v = sw[((size_t)o * IN_DIM + i) * N_COEF + c] * ss[o * IN_DIM + i];
        }
        Wh[t] = __float2half_rn(v);
        return;
    }
    t -= T1;
    if (t < T2) {
        float4 v = *reinterpret_cast<const float4*>(ctxw + t * 4);
        *reinterpret_cast<uint2*>(cwh + t * 4) =
            make_uint2(pack_half2(v.x, v.y), pack_half2(v.z, v.w));
        return;
    }
    t -= T2;
    if (t < nCemb8) {
        const float4* p = reinterpret_cast<const float4*>(cemb) + (size_t)t * 2;
        float4 a = p[0], b = p[1];
        uint4 o;
        o.x = pack_half2(a.x, a.y);
        o.y = pack_half2(a.z, a.w);
        o.z = pack_half2(b.x, b.y);
        o.w = pack_half2(b.z, b.w);
        *reinterpret_cast<uint4*>(ceh + (size_t)t * 8) = o;
    }
}

// ============ ctx GEMM: fp16 single pass ====================================
// xc = cemb @ ctxw^T + bias. BM=128, BN=128, BK=64, 256 thr, 3 stages (96 KB).
#define COFF_A  0
#define COFF_B  16384
#define CSTAGE  32768
#define SMEM_CTX (3 * 32768)

__global__ void __launch_bounds__(256, 1)
ctx_gemm(const half* __restrict__ A, const half* __restrict__ B,
         const float* __restrict__ bias, float* __restrict__ C,
         int M, int N, int K)
{
    extern __shared__ char smem[];
    const uint32_t sbase = smem_u32(smem);
    const int tid = threadIdx.x;
    const int wid = tid >> 5;
    const int lid = tid & 31;
    const int m0 = blockIdx.y * 128;
    const int n0 = blockIdx.x * 128;
    const int warp_m = (wid >> 2) * 64;
    const int warp_n = (wid & 3) * 32;

    float acc[4][4][4];
#pragma unroll
    for (int i = 0; i < 4; ++i)
#pragma unroll
        for (int j = 0; j < 4; ++j)
#pragma unroll
            for (int q = 0; q < 4; ++q) acc[i][j][q] = 0.f;

    auto load_stage = [&](int t, int buf) {
        const uint32_t bb = sbase + buf * CSTAGE;
        const int k0 = t * 64;
        for (int i = tid; i < 1024; i += 256) {
            int row = i >> 3, c = i & 7;
            int m = m0 + row;
            uint32_t v = (m < M) ? 16u : 0u;
            size_t go = (size_t)(m < M ? m : 0) * K + k0 + c * 8;
            uint32_t so = SWZ(row * 128 + c * 16);
            cp16(bb + COFF_A + so, A + go, v);
        }
        for (int i = tid; i < 1024; i += 256) {
            int row = i >> 3, c = i & 7;
            size_t go = (size_t)(n0 + row) * K + k0 + c * 8;
            uint32_t so = SWZ(row * 128 + c * 16);
            cp16(bb + COFF_B + so, B + go, 16u);
        }
        cp_commit();
    };

    const int nk = K / 64;
    load_stage(0, 0);
    if (nk > 1) load_stage(1, 1);

    for (int t = 0; t < nk; ++t) {
        if (t < nk - 1) cp_wait<1>(); else cp_wait<0>();
        __syncthreads();
        if (t + 2 < nk) load_stage(t + 2, (t + 2) % 3);

        const uint32_t bb = sbase + (t % 3) * CSTAGE;
#pragma unroll
        for (int ks = 0; ks < 4; ++ks) {
            uint32_t ah[4][4], bh[4][2];
            {
                uint32_t row_in = ((lid >> 3) & 1) * 8 + (lid & 7);
                uint32_t kb = ks * 32 + (lid >> 4) * 16;
#pragma unroll
                for (int mf = 0; mf < 4; ++mf) {
                    uint32_t off = SWZ((warp_m + mf * 16 + row_in) * 128 + kb);
                    ldm4(ah[mf], bb + COFF_A + off);
                }
            }
            {
                uint32_t row_in = ((lid >> 4) & 1) * 8 + (lid & 7);
                uint32_t kb = ks * 32 + ((lid >> 3) & 1) * 16;
#pragma unroll
                for (int p = 0; p < 2; ++p) {
                    uint32_t off = SWZ((warp_n + p * 16 + row_in) * 128 + kb);
                    uint32_t r[4];
                    ldm4(r, bb + COFF_B + off);
                    bh[2 * p][0] = r[0]; bh[2 * p][1] = r[1];
                    bh[2 * p + 1][0] = r[2]; bh[2 * p + 1][1] = r[3];
                }
            }
#pragma unroll
            for (int mf = 0; mf < 4; ++mf)
#pragma unroll
                for (int nf = 0; nf < 4; ++nf)
                    mma_f16(acc[mf][nf], ah[mf], bh[nf]);
        }
        __syncthreads();
    }

#pragma unroll
    for (int mf = 0; mf < 4; ++mf) {
        int r0 = m0 + warp_m + mf * 16 + (lid >> 2);
#pragma unroll
        for (int nf = 0; nf < 4; ++nf) {
            int col = n0 + warp_n + nf * 8 + (lid & 3) * 2;
            float b0 = bias ? bias[col] : 0.f;
            float b1 = bias ? bias[col + 1] : 0.f;
            if (r0 < M) {
                float2 v = make_float2(acc[mf][nf][0] + b0, acc[mf][nf][1] + b1);
                *reinterpret_cast<float2*>(&C[(size_t)r0 * N + col]) = v;
            }
            if (r0 + 8 < M) {
                float2 v = make_float2(acc[mf][nf][2] + b0, acc[mf][nf][3] + b1);
                *reinterpret_cast<float2*>(&C[(size_t)(r0 + 8) * N + col]) = v;
            }
        }
    }
}

// ============ main GEMM: fp16, 64x64 warp tiles, cross-tile prefetch ========
// 128 threads = 4 warps (2x2); 3-stage ring continuous across tiles
// (nk=48 divisible by 3): at t=nk-2/nk-1 we load the NEXT tile's chunks 0/1,
// so the pipeline never drains at tile switches.
#define MOFF_AH 0
#define MOFF_BH 16384
#define MSTAGE  32768
#define SMEM_MAIN (3 * 32768)

__global__ void __launch_bounds__(128, 2)
main_gemm(const half* __restrict__ Ah, const half* __restrict__ Bh,
          float* __restrict__ C, int M, int ntiles)
{
    extern __shared__ char smem[];
    const uint32_t sbase = smem_u32(smem);
    const int tid = threadIdx.x;
    const int wid = tid >> 5;
    const int lid = tid & 31;
    const int warp_m = (wid >> 1) * 64;
    const int warp_n = (wid & 1) * 64;
    const int nk = K_TOTAL / 64;          // 48

    auto load_stage = [&](int m0, int n0, int t, int buf) {
        const uint32_t bb = sbase + buf * MSTAGE;
        const int k0 = t * 64;
        for (int i = tid; i < 1024; i += 128) {
            int row = i >> 3, c = i & 7;
            int m = m0 + row;
            uint32_t v = (m < M) ? 16u : 0u;
            uint32_t so = SWZ(row * 128 + c * 16);
            cp16(bb + MOFF_AH + so,
                 Ah + (size_t)(m < M ? m : 0) * K_TOTAL + k0 + c * 8, v);
        }
        for (int i = tid; i < 1024; i += 128) {
            int row = i >> 3, c = i & 7;
            size_t go = (size_t)(n0 + row) * K_TOTAL + k0 + c * 8;
            uint32_t so = SWZ(row * 128 + c * 16);
            cp16(bb + MOFF_BH + so, Bh + go, 16u);
        }
        cp_commit();
    };

    int tile = blockIdx.x;
    if (tile >= ntiles) return;
    int m0 = (tile >> 1) * 128;
    int n0 = (tile & 1) * 128;

    load_stage(m0, n0, 0, 0);
    load_stage(m0, n0, 1, 1);

    while (true) {
        const int ntile = tile + gridDim.x;
        const bool hasnext = ntile < ntiles;
        const int nm0 = (ntile >> 1) * 128;
        const int nn0 = (ntile & 1) * 128;

        float acc[4][8][4];
#pragma unroll
        for (int i = 0; i < 4; ++i)
#pragma unroll
            for (int j = 0; j < 8; ++j)
#pragma unroll
                for (int q = 0; q < 4; ++q) acc[i][j][q] = 0.f;

        for (int t = 0; t < nk; ++t) {
            if (!hasnext && t == nk - 1) cp_wait<0>(); else cp_wait<1>();
            __syncthreads();
            // issue load for chunk t+2 (wraps into next tile's chunks 0/1)
            if (t + 2 < nk)      load_stage(m0, n0, t + 2, (t + 2) % 3);
            else if (hasnext)    load_stage(nm0, nn0, t + 2 - nk, (t + 2) % 3);

            const uint32_t bb = sbase + (t % 3) * MSTAGE;
#pragma unroll
            for (int ks = 0; ks < 4; ++ks) {
                uint32_t ah[4][4], bh[8][2];
                {
                    uint32_t row_in = ((lid >> 3) & 1) * 8 + (lid & 7);
                    uint32_t kb = ks * 32 + (lid >> 4) * 16;
#pragma unroll
                    for (int mf = 0; mf < 4; ++mf) {
                        uint32_t off = SWZ((warp_m + mf * 16 + row_in) * 128 + kb);
                        ldm4(ah[mf], bb + MOFF_AH + off);
                    }
                }
                {
                    uint32_t row_in = ((lid >> 4) & 1) * 8 + (lid & 7);
                    uint32_t kb = ks * 32 + ((lid >> 3) & 1) * 16;
#pragma unroll
                    for (int p = 0; p < 4; ++p) {
                        uint32_t off = SWZ((warp_n + p * 16 + row_in) * 128 + kb);
                        uint32_t r[4];
                        ldm4(r, bb + MOFF_BH + off);
                        bh[2 * p][0] = r[0]; bh[2 * p][1] = r[1];
                        bh[2 * p + 1][0] = r[2]; bh[2 * p + 1][1] = r[3];
                    }
                }
#pragma unroll
                for (int mf = 0; mf < 4; ++mf)
#pragma unroll
                    for (int nf = 0; nf < 8; ++nf)
                        mma_f16(acc[mf][nf], ah[mf], bh[nf]);
            }
        }

        // epilogue (registers -> global; overlaps in-flight next-tile loads)
#pragma unroll
        for (int mf = 0; mf < 4; ++mf) {
            int r0 = m0 + warp_m + mf * 16 + (lid >> 2);
#pragma unroll
            for (int nf = 0; nf < 8; ++nf) {
                int col = n0 + warp_n + nf * 8 + (lid & 3) * 2;
                if (r0 < M) {
                    float2 v = make_float2(acc[mf][nf][0], acc[mf][nf][1]);
                    *reinterpret_cast<float2*>(&C[(size_t)r0 * OUT_DIM + col]) = v;
                }
                if (r0 + 8 < M) {
                    float2 v = make_float2(acc[mf][nf][2], acc[mf][nf][3]);
                    *reinterpret_cast<float2*>(&C[(size_t)(r0 + 8) * OUT_DIM + col]) = v;
                }
            }
        }

        if (!hasnext) break;
        tile = ntile;
        m0 = nm0;
        n0 = nn0;
    }
}

// ---------------- activation builder: vectorized, cardinal spline -----------
__global__ void build_act(const float* __restrict__ node, const float* __restrict__ xc,
                          const int* __restrict__ pairs, const float* __restrict__ gridp,
                          half* __restrict__ acth, int nEdges)
{
    int t = blockIdx.x * blockDim.x + threadIdx.x;
    if (t >= nEdges * 48) return;
    int n = t / 48;
    int sub = t - n * 48;
    int i0 = sub * 8;

    const float g0 = gridp[0];
    const float rh = 1.f / (gridp[1] - g0);

    const float* src;
    if (i0 < NODE_DIM)
        src = node + (size_t)pairs[2 * n] * NODE_DIM + i0;
    else if (i0 < 2 * NODE_DIM)
        src = node + (size_t)pairs[2 * n + 1] * NODE_DIM + (i0 - NODE_DIM);
    else
        src = xc + (size_t)n * NODE_DIM + (i0 - 2 * NODE_DIM);

    float4 xa = *reinterpret_cast<const float4*>(src);
    float4 xb = *reinterpret_cast<const float4*>(src + 4);
    float xs[8] = {xa.x, xa.y, xa.z, xa.w, xb.x, xb.y, xb.z, xb.w};

    uint32_t pl[8][4];
#pragma unroll
    for (int q = 0; q < 4; ++q) {
        float v0[8], v1[8];
        silu_spline(xs[2 * q], g0, rh, v0);
        silu_spline(xs[2 * q + 1], g0, rh, v1);
#pragma unroll
        for (int j = 0; j < 8; ++j)
            pl[j][q] = pack_half2(v0[j], v1[j]);
    }

    size_t base = (size_t)n * K_TOTAL;
#pragma unroll
    for (int j = 0; j < 8; ++j)
        *reinterpret_cast<uint4*>(acth + base + (size_t)j * IN_DIM + i0) =
            make_uint4(pl[j][0], pl[j][1], pl[j][2], pl[j][3]);
}

// ---------------------------------------------------------------------------
extern "C" void kernel_launch(void* const* d_in, const int* in_sizes, int n_in,
                              void* d_out, int out_size)
{
    const float* node  = (const float*)d_in[0];
    const float* cemb  = (const float*)d_in[1];
    const int*   pairs = (const int*)  d_in[2];
    const float* ctxw  = (const float*)d_in[3];
    const float* ctxb  = (const float*)d_in[4];
    const float* bw    = (const float*)d_in[5];
    const float* sw    = (const float*)d_in[6];
    const float* ss    = (const float*)d_in[7];
    const float* grid  = (const float*)d_in[8];
    float* out = (float*)d_out;

    int nEdges = in_sizes[2] / 2;

    float *xc;
    half *acth, *wh, *ceh, *cwh;
    cudaGetSymbolAddress((void**)&xc, g_xc);
    cudaGetSymbolAddress((void**)&acth, g_act_h);
    cudaGetSymbolAddress((void**)&wh, g_w_h);
    cudaGetSymbolAddress((void**)&ceh, g_cemb_h);
    cudaGetSymbolAddress((void**)&cwh, g_cw_h);

    cudaFuncSetAttribute(ctx_gemm, cudaFuncAttributeMaxDynamicSharedMemorySize, SMEM_CTX);
    cudaFuncSetAttribute(main_gemm, cudaFuncAttributeMaxDynamicSharedMemorySize, SMEM_MAIN);

    // fused prep: weights + ctxw convert + cemb convert
    {
        int nCemb8 = nEdges * CTX_DIM / 8;
        int total = OUT_DIM * K_TOTAL + (NODE_DIM * CTX_DIM) / 4 + nCemb8;
        prep_all<<<(total + 255) / 256, 256>>>(bw, sw, ss, wh, ctxw, cwh,
                                               cemb, ceh, nCemb8);
    }

    // ctx projection  xc = cemb @ ctxw^T + b  (M=nEdges, N=128, K=256)
    {
        dim3 g(1, (nEdges + 127) / 128);
        ctx_gemm<<<g, 256, SMEM_CTX>>>(ceh, cwh, ctxb, xc,
                                       nEdges, NODE_DIM, CTX_DIM);
    }

    // activations (fp16, vectorized)
    {
        int total = nEdges * 48;
        build_act<<<(total + 255) / 256, 256>>>(node, xc, pairs, grid, acth, nEdges);
    }

    // main GEMM  out = act @ weff^T, persistent + cross-tile prefetch
    {
        int ntiles = ((nEdges + 127) / 128) * 2;
        int blocks = ntiles < 296 ? ntiles : 296;
        main_gemm<<<blocks, 128, SMEM_MAIN>>>(acth, wh, out, nEdges, ntiles);
    }
}